// round 1
// baseline (speedup 1.0000x reference)
#include <cuda_runtime.h>
#include <cuda_bf16.h>

#define N_NODES 50000
#define N_EDGES 800000
#define N_GRAPHS 128
#define DIM 128
#define OUTD 64
#define BN_EPS 1e-5f

// ---------------- scratch (device globals; no runtime allocation) ----------------
__device__ float g_H[N_NODES * DIM];        // current hidden rep (post BN+relu)
__device__ float g_Z[N_NODES * DIM];        // agg+h  /  reused as z2 output
__device__ float g_Z1[N_NODES * DIM];       // first-GEMM output (pre-BN1)
__device__ float g_pooled[5 * N_GRAPHS * DIM];
__device__ float g_stats[256];              // [0:128) col sums, [128:256) col sumsq
__device__ float g_aff1[256];               // [0:128) a, [128:256) c
__device__ float g_aff2[256];

// ---------------- helpers ----------------
__device__ __forceinline__ void red_add_f32x4(float* p, float4 v) {
    asm volatile("red.global.add.v4.f32 [%0], {%1,%2,%3,%4};"
                 :: "l"(p), "f"(v.x), "f"(v.y), "f"(v.z), "f"(v.w) : "memory");
}

// ---------------- Z = H (vectorized copy) ----------------
__global__ void copy_k(const float* __restrict__ src, float* __restrict__ dst) {
    int i = blockIdx.x * 256 + threadIdx.x;     // float4 index; grid covers exactly
    reinterpret_cast<float4*>(dst)[i] = reinterpret_cast<const float4*>(src)[i];
}

// ---------------- edge scatter: Z[dst] += H[src]  (1 warp per edge) ----------------
__global__ void scatter_k(const float* __restrict__ H, const int* __restrict__ src,
                          const int* __restrict__ dst, float* __restrict__ Z) {
    int gid = blockIdx.x * 256 + threadIdx.x;
    int e = gid >> 5;
    int c = gid & 31;                            // float4 chunk within the 128-d row
    int s = src[e];
    int d = dst[e];
    float4 v = reinterpret_cast<const float4*>(H)[(size_t)s * 32 + c];
    red_add_f32x4(Z + (size_t)d * DIM + c * 4, v);
}

// ---------------- GEMM 50000x128 @ 128x128, optional fused BN-affine+relu on A,
//                  epilogue computes per-column sum / sumsq partials ----------------
// BM=64, BN=128, BK=128 (full K). 256 threads, 4x8 register tile.
// smem: As transposed [128][68], Bs [128][128]. 100352 B -> 2 CTAs/SM.
template <bool TRANS>
__global__ void __launch_bounds__(256)
gemm_bn_k(const float* __restrict__ A, const float* __restrict__ W,
          float* __restrict__ C, const float* __restrict__ aff,
          float* __restrict__ stats) {
    extern __shared__ float sm[];
    float* As = sm;                  // [k][r] : As[k*68 + r]
    float* Bs = sm + 128 * 68;       // [k][c] : Bs[k*128 + c]

    const int t  = threadIdx.x;
    const int tx = t & 15;           // col group (8 cols each)
    const int ty = t >> 4;           // row group (4 rows each)
    const int rowBase = blockIdx.x * 64;

    // load B tile: 128x128 floats = 4096 float4 / 256 threads = 16 each
#pragma unroll
    for (int j = 0; j < 16; ++j) {
        int idx = t + j * 256;
        reinterpret_cast<float4*>(Bs)[idx] = reinterpret_cast<const float4*>(W)[idx];
    }
    // load A tile: 64x128 floats = 2048 float4 / 256 = 8 each; store transposed
#pragma unroll
    for (int j = 0; j < 8; ++j) {
        int idx = t + j * 256;
        int r = idx >> 5;            // local row 0..63
        int q = idx & 31;            // float4 quad along k
        int grow = rowBase + r;
        float4 v = make_float4(0.f, 0.f, 0.f, 0.f);
        if (grow < N_NODES)
            v = reinterpret_cast<const float4*>(A)[(size_t)grow * 32 + q];
        if (TRANS) {
            float4 a4 = __ldg(reinterpret_cast<const float4*>(aff) + q);
            float4 c4 = __ldg(reinterpret_cast<const float4*>(aff + 128) + q);
            v.x = fmaxf(fmaf(v.x, a4.x, c4.x), 0.f);
            v.y = fmaxf(fmaf(v.y, a4.y, c4.y), 0.f);
            v.z = fmaxf(fmaf(v.z, a4.z, c4.z), 0.f);
            v.w = fmaxf(fmaf(v.w, a4.w, c4.w), 0.f);
        }
        int k0 = q * 4;
        As[(k0 + 0) * 68 + r] = v.x;
        As[(k0 + 1) * 68 + r] = v.y;
        As[(k0 + 2) * 68 + r] = v.z;
        As[(k0 + 3) * 68 + r] = v.w;
    }
    __syncthreads();

    float acc[4][8];
#pragma unroll
    for (int i = 0; i < 4; ++i)
#pragma unroll
        for (int j = 0; j < 8; ++j) acc[i][j] = 0.f;

#pragma unroll 8
    for (int k = 0; k < 128; ++k) {
        float4 a4 = *reinterpret_cast<const float4*>(As + k * 68 + (ty << 2));
        float4 b0 = *reinterpret_cast<const float4*>(Bs + k * 128 + (tx << 3));
        float4 b1 = *reinterpret_cast<const float4*>(Bs + k * 128 + (tx << 3) + 4);
        float av[4] = {a4.x, a4.y, a4.z, a4.w};
        float bv[8] = {b0.x, b0.y, b0.z, b0.w, b1.x, b1.y, b1.z, b1.w};
#pragma unroll
        for (int i = 0; i < 4; ++i)
#pragma unroll
            for (int j = 0; j < 8; ++j)
                acc[i][j] = fmaf(av[i], bv[j], acc[i][j]);
    }

    // store + per-column partial stats (only valid rows)
    float psum[8], psq[8];
#pragma unroll
    for (int j = 0; j < 8; ++j) { psum[j] = 0.f; psq[j] = 0.f; }
#pragma unroll
    for (int i = 0; i < 4; ++i) {
        int grow = rowBase + ty * 4 + i;
        if (grow < N_NODES) {
            float4 o0 = make_float4(acc[i][0], acc[i][1], acc[i][2], acc[i][3]);
            float4 o1 = make_float4(acc[i][4], acc[i][5], acc[i][6], acc[i][7]);
            reinterpret_cast<float4*>(C)[(size_t)grow * 32 + tx * 2 + 0] = o0;
            reinterpret_cast<float4*>(C)[(size_t)grow * 32 + tx * 2 + 1] = o1;
#pragma unroll
            for (int j = 0; j < 8; ++j) {
                psum[j] += acc[i][j];
                psq[j]  += acc[i][j] * acc[i][j];
            }
        }
    }
    __syncthreads();                 // As no longer needed; reuse for reduction
    float* red = sm;                 // [16][256] : sums then sumsq per row-group
#pragma unroll
    for (int j = 0; j < 8; ++j) {
        red[ty * 256 + tx * 8 + j]       = psum[j];
        red[ty * 256 + 128 + tx * 8 + j] = psq[j];
    }
    __syncthreads();
    {
        float s = 0.f;
#pragma unroll
        for (int r = 0; r < 16; ++r) s += red[r * 256 + t];
        atomicAdd(&stats[t], s);     // t<128: sum, t>=128: sumsq
    }
}

// ---------------- stats -> affine (a = g*rsqrt(var+eps), c = b - mean*a) ----------------
__global__ void affine_k(const float* __restrict__ stats, const float* __restrict__ g,
                         const float* __restrict__ b, float* __restrict__ aff) {
    int t = threadIdx.x;             // 128
    const float invN = 1.0f / (float)N_NODES;
    float mean = stats[t] * invN;
    float var  = stats[128 + t] * invN - mean * mean;
    float inv  = rsqrtf(var + BN_EPS);
    float a    = g[t] * inv;
    aff[t]       = a;
    aff[128 + t] = b[t] - mean * a;
}

// ---------------- pool raw input h into pooled[0] ----------------
__global__ void pool_in_k(const float* __restrict__ h, const int* __restrict__ gidx,
                          float* __restrict__ pooled) {
    int gid = blockIdx.x * 256 + threadIdx.x;
    int node = gid >> 5;
    int c = gid & 31;
    float4 v = reinterpret_cast<const float4*>(h)[(size_t)node * 32 + c];
    int gr = gidx[node];
    red_add_f32x4(pooled + (size_t)gr * DIM + c * 4, v);
}

// ---------------- H = relu(Z*a + c); pooled[layer] += H ----------------
__global__ void pool_act_k(const float* __restrict__ Z, const float* __restrict__ aff,
                           const int* __restrict__ gidx, float* __restrict__ H,
                           float* __restrict__ pooled) {
    int gid = blockIdx.x * 256 + threadIdx.x;
    int node = gid >> 5;
    int c = gid & 31;
    float4 v  = reinterpret_cast<const float4*>(Z)[(size_t)node * 32 + c];
    float4 a4 = __ldg(reinterpret_cast<const float4*>(aff) + c);
    float4 c4 = __ldg(reinterpret_cast<const float4*>(aff + 128) + c);
    v.x = fmaxf(fmaf(v.x, a4.x, c4.x), 0.f);
    v.y = fmaxf(fmaf(v.y, a4.y, c4.y), 0.f);
    v.z = fmaxf(fmaf(v.z, a4.z, c4.z), 0.f);
    v.w = fmaxf(fmaf(v.w, a4.w, c4.w), 0.f);
    reinterpret_cast<float4*>(H)[(size_t)node * 32 + c] = v;
    int gr = gidx[node];
    red_add_f32x4(pooled + (size_t)gr * DIM + c * 4, v);
}

// ---------------- score[g][o] = sum_i pooled[i][g] . predW[i][:,o] + sum_i predb[i][o] ----------------
__global__ void score_k(const float* __restrict__ pooled, const float* __restrict__ predW,
                        const float* __restrict__ predb, float* __restrict__ out) {
    int g = blockIdx.x;              // 128
    int o = threadIdx.x;             // 64
    __shared__ float sp[5 * DIM];
    for (int idx = o; idx < 5 * DIM; idx += 64)
        sp[idx] = pooled[(size_t)(idx / DIM) * (N_GRAPHS * DIM) + (size_t)g * DIM + (idx % DIM)];
    __syncthreads();
    float acc = 0.f;
#pragma unroll
    for (int i = 0; i < 5; ++i) acc += predb[i * OUTD + o];
    for (int i = 0; i < 5; ++i) {
#pragma unroll 4
        for (int k = 0; k < DIM; ++k)
            acc = fmaf(sp[i * DIM + k], predW[((size_t)i * DIM + k) * OUTD + o], acc);
    }
    out[(size_t)g * OUTD + o] = acc;
}

// ---------------- launch ----------------
extern "C" void kernel_launch(void* const* d_in, const int* in_sizes, int n_in,
                              void* d_out, int out_size) {
    const float* h      = (const float*)d_in[0];
    const int*   esrc   = (const int*)  d_in[1];
    const int*   edst   = (const int*)  d_in[2];
    const int*   gids   = (const int*)  d_in[3];
    const float* W1     = (const float*)d_in[4];
    const float* bn1_g  = (const float*)d_in[5];
    const float* bn1_b  = (const float*)d_in[6];
    const float* W2     = (const float*)d_in[7];
    const float* bn2_g  = (const float*)d_in[8];
    const float* bn2_b  = (const float*)d_in[9];
    const float* predW  = (const float*)d_in[10];
    const float* predb  = (const float*)d_in[11];
    float* out = (float*)d_out;

    float *pH, *pZ, *pZ1, *pPooled, *pStats, *pAff1, *pAff2;
    cudaGetSymbolAddress((void**)&pH, g_H);
    cudaGetSymbolAddress((void**)&pZ, g_Z);
    cudaGetSymbolAddress((void**)&pZ1, g_Z1);
    cudaGetSymbolAddress((void**)&pPooled, g_pooled);
    cudaGetSymbolAddress((void**)&pStats, g_stats);
    cudaGetSymbolAddress((void**)&pAff1, g_aff1);
    cudaGetSymbolAddress((void**)&pAff2, g_aff2);

    const int SMEM = (128 * 68 + 128 * 128) * (int)sizeof(float);   // 100352 B
    cudaFuncSetAttribute(gemm_bn_k<false>, cudaFuncAttributeMaxDynamicSharedMemorySize, SMEM);
    cudaFuncSetAttribute(gemm_bn_k<true>,  cudaFuncAttributeMaxDynamicSharedMemorySize, SMEM);

    const int COPY_BLOCKS = (N_NODES * 32) / 256;       // 6250
    const int EDGE_BLOCKS = (N_EDGES * 32) / 256;       // 100000
    const int GEMM_BLOCKS = (N_NODES + 63) / 64;        // 782

    cudaMemsetAsync(pPooled, 0, 5 * N_GRAPHS * DIM * sizeof(float), 0);
    pool_in_k<<<COPY_BLOCKS, 256>>>(h, gids, pPooled);

    for (int i = 0; i < 4; ++i) {
        const float* Hsrc = (i == 0) ? h : pH;
        copy_k<<<COPY_BLOCKS, 256>>>(Hsrc, pZ);
        scatter_k<<<EDGE_BLOCKS, 256>>>(Hsrc, esrc, edst, pZ);

        cudaMemsetAsync(pStats, 0, 256 * sizeof(float), 0);
        gemm_bn_k<false><<<GEMM_BLOCKS, 256, SMEM>>>(pZ, W1 + (size_t)i * DIM * DIM,
                                                     pZ1, nullptr, pStats);
        affine_k<<<1, 128>>>(pStats, bn1_g + i * DIM, bn1_b + i * DIM, pAff1);

        cudaMemsetAsync(pStats, 0, 256 * sizeof(float), 0);
        gemm_bn_k<true><<<GEMM_BLOCKS, 256, SMEM>>>(pZ1, W2 + (size_t)i * DIM * DIM,
                                                    pZ, pAff1, pStats);
        affine_k<<<1, 128>>>(pStats, bn2_g + i * DIM, bn2_b + i * DIM, pAff2);

        pool_act_k<<<COPY_BLOCKS, 256>>>(pZ, pAff2, gids, pH,
                                         pPooled + (size_t)(i + 1) * N_GRAPHS * DIM);
    }

    score_k<<<N_GRAPHS, OUTD>>>(pPooled, predW, predb, out);
}

// round 3
// speedup vs baseline: 1.7590x; 1.7590x over previous
#include <cuda_runtime.h>
#include <cuda_bf16.h>
#include <cstdint>

#define N_NODES 50000
#define N_EDGES 800000
#define N_GRAPHS 128
#define DIM 128
#define OUTD 64
#define BN_EPS 1e-5f

// ---------------- scratch (device globals; no runtime allocation) ----------------
__device__ float g_H[N_NODES * DIM];
__device__ float g_Z[N_NODES * DIM];
__device__ float g_Z1[N_NODES * DIM];
__device__ float g_pooled[5 * N_GRAPHS * DIM];
__device__ float g_stats[256];
__device__ float g_aff1[256];
__device__ float g_aff2[256];
// weight fragments: [mat8][oper2(hi,lo)][kstep8][warp_n2][lane32][16 u32]
__device__ uint32_t g_WF[8 * 16384];
// CSR scratch
__device__ int g_deg[N_NODES];
__device__ int g_rowstart[N_NODES + 1];
__device__ int g_cursor[N_NODES];
__device__ int g_csr[N_EDGES];

// ---------------- helpers ----------------
__device__ __forceinline__ uint32_t smem_u32(const void* p) {
    uint32_t a;
    asm("{ .reg .u64 t; cvta.to.shared.u64 t, %1; cvt.u32.u64 %0, t; }" : "=r"(a) : "l"(p));
    return a;
}
__device__ __forceinline__ void red_add_f32x4(float* p, float4 v) {
    asm volatile("red.global.add.v4.f32 [%0], {%1,%2,%3,%4};"
                 :: "l"(p), "f"(v.x), "f"(v.y), "f"(v.z), "f"(v.w) : "memory");
}
__device__ __forceinline__ void ldmatrix_x4(uint32_t* r, uint32_t addr) {
    asm volatile("ldmatrix.sync.aligned.m8n8.x4.shared.b16 {%0,%1,%2,%3}, [%4];"
                 : "=r"(r[0]), "=r"(r[1]), "=r"(r[2]), "=r"(r[3]) : "r"(addr));
}
__device__ __forceinline__ void mma16816(float* c, const uint32_t* a, uint32_t b0, uint32_t b1) {
    asm volatile(
        "mma.sync.aligned.m16n8k16.row.col.f32.bf16.bf16.f32 "
        "{%0,%1,%2,%3}, {%4,%5,%6,%7}, {%8,%9}, {%0,%1,%2,%3};"
        : "+f"(c[0]), "+f"(c[1]), "+f"(c[2]), "+f"(c[3])
        : "r"(a[0]), "r"(a[1]), "r"(a[2]), "r"(a[3]), "r"(b0), "r"(b1));
}
__device__ __forceinline__ uint32_t pack_bf16(float lo, float hi) {
    __nv_bfloat162 p = __floats2bfloat162_rn(lo, hi);  // .x = lo half (low 16 bits)
    return *reinterpret_cast<uint32_t*>(&p);
}

// ---------------- weight fragment pre-pack ----------------
// one thread per (mat, ks, wn, lane, j): writes hi and lo fragment words.
__global__ void conv_w_k(const float* __restrict__ W1, const float* __restrict__ W2,
                         uint32_t* __restrict__ WF) {
    int gid = blockIdx.x * 256 + threadIdx.x;   // 65536 total
    int j    = gid & 15;
    int lane = (gid >> 4) & 31;
    int wn   = (gid >> 9) & 1;
    int ks   = (gid >> 10) & 7;
    int mat  = gid >> 13;
    const float* W = (mat < 4) ? (W1 + (size_t)mat * 16384)
                               : (W2 + (size_t)(mat - 4) * 16384);
    int k0 = ks * 16 + (lane & 3) * 2 + (j & 1) * 8;
    int n  = wn * 64 + (j >> 1) * 8 + (lane >> 2);
    float w0 = W[k0 * 128 + n];
    float w1 = W[(k0 + 1) * 128 + n];
    __nv_bfloat16 h0 = __float2bfloat16_rn(w0), h1 = __float2bfloat16_rn(w1);
    float l0 = w0 - __bfloat162float(h0), l1 = w1 - __bfloat162float(h1);
    uint32_t hi = ((uint32_t)__bfloat16_as_ushort(h1) << 16) | __bfloat16_as_ushort(h0);
    uint32_t lo = pack_bf16(l0, l1);
    size_t base = (size_t)mat * 16384 + (size_t)ks * 1024 + (size_t)wn * 512 + (size_t)lane * 16 + j;
    WF[base] = hi;             // oper 0 (hi)
    WF[base + 8192] = lo;      // oper 1 (lo)
}

// ---------------- tensor GEMM: C[50000x128] = A @ W, split-bf16 x3, fp32 accum ----
// CTA: 128 rows x 128 cols, 256 threads (8 warps: wm = wid>>1 rows, wn = wid&1 cols).
template <bool AFF>
__global__ void __launch_bounds__(256)
gemm_mma_k(const float* __restrict__ A, const uint4* __restrict__ WF4,
           float* __restrict__ C, const float* __restrict__ aff) {
    extern __shared__ __align__(16) __nv_bfloat16 smA[];   // Ah[16384], Al[16384]
    __nv_bfloat16* Ah = smA;
    __nv_bfloat16* Al = smA + 16384;
    const int t = threadIdx.x;
    const int lane = t & 31;
    const int wid = t >> 5;
    const int wm = wid >> 1, wn = wid & 1;
    const int rowBase = blockIdx.x * 128;

    // ---- load A tile, optional BN-affine+relu, split hi/lo, swizzled smem store ----
#pragma unroll
    for (int jj = 0; jj < 8; ++jj) {
        int idx = t + jj * 256;        // 2048 16B-units
        int r = idx >> 4;              // local row
        int u = idx & 15;              // unit (8 bf16 = 8 cols)
        int grow = rowBase + r;
        float f[8];
        if (grow < N_NODES) {
            float4 v0 = reinterpret_cast<const float4*>(A)[(size_t)grow * 32 + u * 2];
            float4 v1 = reinterpret_cast<const float4*>(A)[(size_t)grow * 32 + u * 2 + 1];
            if (AFF) {
                float4 a0 = __ldg(reinterpret_cast<const float4*>(aff) + u * 2);
                float4 a1 = __ldg(reinterpret_cast<const float4*>(aff) + u * 2 + 1);
                float4 c0 = __ldg(reinterpret_cast<const float4*>(aff + 128) + u * 2);
                float4 c1 = __ldg(reinterpret_cast<const float4*>(aff + 128) + u * 2 + 1);
                v0.x = fmaxf(fmaf(v0.x, a0.x, c0.x), 0.f);
                v0.y = fmaxf(fmaf(v0.y, a0.y, c0.y), 0.f);
                v0.z = fmaxf(fmaf(v0.z, a0.z, c0.z), 0.f);
                v0.w = fmaxf(fmaf(v0.w, a0.w, c0.w), 0.f);
                v1.x = fmaxf(fmaf(v1.x, a1.x, c1.x), 0.f);
                v1.y = fmaxf(fmaf(v1.y, a1.y, c1.y), 0.f);
                v1.z = fmaxf(fmaf(v1.z, a1.z, c1.z), 0.f);
                v1.w = fmaxf(fmaf(v1.w, a1.w, c1.w), 0.f);
            }
            f[0] = v0.x; f[1] = v0.y; f[2] = v0.z; f[3] = v0.w;
            f[4] = v1.x; f[5] = v1.y; f[6] = v1.z; f[7] = v1.w;
        } else {
#pragma unroll
            for (int i = 0; i < 8; ++i) f[i] = 0.f;
        }
        uint32_t hw[4], lw[4];
#pragma unroll
        for (int i = 0; i < 4; ++i) {
            __nv_bfloat16 ha = __float2bfloat16_rn(f[2 * i]);
            __nv_bfloat16 hb = __float2bfloat16_rn(f[2 * i + 1]);
            float ra = f[2 * i] - __bfloat162float(ha);
            float rb = f[2 * i + 1] - __bfloat162float(hb);
            hw[i] = ((uint32_t)__bfloat16_as_ushort(hb) << 16) | __bfloat16_as_ushort(ha);
            lw[i] = pack_bf16(ra, rb);
        }
        int su = u ^ (r & 7);
        reinterpret_cast<uint4*>(Ah)[r * 16 + su] = make_uint4(hw[0], hw[1], hw[2], hw[3]);
        reinterpret_cast<uint4*>(Al)[r * 16 + su] = make_uint4(lw[0], lw[1], lw[2], lw[3]);
    }
    __syncthreads();

    // ---- mma mainloop ----
    float acc[2][8][4];
#pragma unroll
    for (int mt = 0; mt < 2; ++mt)
#pragma unroll
        for (int nt = 0; nt < 8; ++nt)
#pragma unroll
            for (int i = 0; i < 4; ++i) acc[mt][nt][i] = 0.f;

    const uint32_t AhB = smem_u32(Ah);
    const uint32_t AlB = smem_u32(Al);
    // per-lane B pointers (uint4 index): [oper*2048] + ks*256 + wn*128 + lane*4
    const uint4* bhp = WF4 + wn * 128 + lane * 4;
    const uint4* blp = bhp + 2048;

#pragma unroll
    for (int ks = 0; ks < 8; ++ks) {
        uint32_t ah[2][4], al[2][4];
#pragma unroll
        for (int mt = 0; mt < 2; ++mt) {
            int row = wm * 32 + mt * 16 + (lane & 15);
            int unit = ks * 2 + (lane >> 4);
            int su = unit ^ (row & 7);
            uint32_t off = (uint32_t)(row * 256 + su * 16);
            ldmatrix_x4(ah[mt], AhB + off);
            ldmatrix_x4(al[mt], AlB + off);
        }
#pragma unroll
        for (int p = 0; p < 4; ++p) {
            uint4 vh = __ldg(bhp + ks * 256 + p);
            uint4 vl = __ldg(blp + ks * 256 + p);
            // nt = 2p : (vh.x, vh.y);  nt = 2p+1 : (vh.z, vh.w)
            mma16816(acc[0][2 * p],     ah[0], vh.x, vh.y);
            mma16816(acc[1][2 * p],     ah[1], vh.x, vh.y);
            mma16816(acc[0][2 * p + 1], ah[0], vh.z, vh.w);
            mma16816(acc[1][2 * p + 1], ah[1], vh.z, vh.w);
            mma16816(acc[0][2 * p],     al[0], vh.x, vh.y);
            mma16816(acc[1][2 * p],     al[1], vh.x, vh.y);
            mma16816(acc[0][2 * p + 1], al[0], vh.z, vh.w);
            mma16816(acc[1][2 * p + 1], al[1], vh.z, vh.w);
            mma16816(acc[0][2 * p],     ah[0], vl.x, vl.y);
            mma16816(acc[1][2 * p],     ah[1], vl.x, vl.y);
            mma16816(acc[0][2 * p + 1], ah[0], vl.z, vl.w);
            mma16816(acc[1][2 * p + 1], ah[1], vl.z, vl.w);
        }
    }

    // ---- epilogue: direct float2 stores ----
#pragma unroll
    for (int mt = 0; mt < 2; ++mt) {
        int row = rowBase + wm * 32 + mt * 16 + (lane >> 2);
        if (row < N_NODES) {
#pragma unroll
            for (int nt = 0; nt < 8; ++nt) {
                int col = wn * 64 + nt * 8 + (lane & 3) * 2;
                *reinterpret_cast<float2*>(C + (size_t)row * 128 + col) =
                    make_float2(acc[mt][nt][0], acc[mt][nt][1]);
            }
        }
        if (row + 8 < N_NODES) {
#pragma unroll
            for (int nt = 0; nt < 8; ++nt) {
                int col = wn * 64 + nt * 8 + (lane & 3) * 2;
                *reinterpret_cast<float2*>(C + (size_t)(row + 8) * 128 + col) =
                    make_float2(acc[mt][nt][2], acc[mt][nt][3]);
            }
        }
    }
}

// ---------------- CSR build ----------------
__global__ void deg_k(const int* __restrict__ edst, int* __restrict__ deg) {
    int e = blockIdx.x * 256 + threadIdx.x;   // exactly 800000
    atomicAdd(&deg[edst[e]], 1);
}

__global__ void scan_k(const int* __restrict__ deg, int* __restrict__ rowstart,
                       int* __restrict__ cursor) {
    __shared__ int ssum[1024];
    int t = threadIdx.x;
    const int CH = (N_NODES + 1023) / 1024;   // 49
    int base = t * CH;
    int s = 0;
    for (int j = 0; j < CH; ++j) {
        int i = base + j;
        if (i < N_NODES) s += deg[i];
    }
    ssum[t] = s;
    __syncthreads();
    for (int off = 1; off < 1024; off <<= 1) {
        int v = (t >= off) ? ssum[t - off] : 0;
        __syncthreads();
        ssum[t] += v;
        __syncthreads();
    }
    int pre = (t == 0) ? 0 : ssum[t - 1];
    for (int j = 0; j < CH; ++j) {
        int i = base + j;
        if (i < N_NODES) {
            rowstart[i] = pre;
            cursor[i] = pre;
            pre += deg[i];
        }
    }
    if (t == 0) rowstart[N_NODES] = N_EDGES;
}

__global__ void fill_k(const int* __restrict__ esrc, const int* __restrict__ edst,
                       int* __restrict__ cursor, int* __restrict__ csr) {
    int e = blockIdx.x * 256 + threadIdx.x;
    int p = atomicAdd(&cursor[edst[e]], 1);
    csr[p] = esrc[e];
}

// ---------------- aggregation: Z[node] = H[node] + sum_{s in CSR(node)} H[s] --------
__global__ void __launch_bounds__(256) agg_k(const float* __restrict__ H,
                                             const int* __restrict__ rs,
                                             const int* __restrict__ csr,
                                             float* __restrict__ Z) {
    int gid = blockIdx.x * 256 + threadIdx.x;
    int node = gid >> 5;
    int lane = gid & 31;
    int s0 = __ldg(rs + node);
    int s1 = __ldg(rs + node + 1);
    float4 v = reinterpret_cast<const float4*>(H)[(size_t)node * 32 + lane];
    for (int j = s0; j < s1; ++j) {
        int s = __ldg(csr + j);
        float4 u = reinterpret_cast<const float4*>(H)[(size_t)s * 32 + lane];
        v.x += u.x; v.y += u.y; v.z += u.z; v.w += u.w;
    }
    reinterpret_cast<float4*>(Z)[(size_t)node * 32 + lane] = v;
}

// ---------------- column stats: sums / sumsq over 50000 rows ----------------
__global__ void __launch_bounds__(256) stats_k(const float* __restrict__ X,
                                               float* __restrict__ stats) {
    const int t = threadIdx.x;
    const int c4 = t & 31;
    const int rg = t >> 5;
    float4 s = make_float4(0.f, 0.f, 0.f, 0.f);
    float4 q = make_float4(0.f, 0.f, 0.f, 0.f);
    int r = blockIdx.x * 200 + rg;
#pragma unroll 5
    for (int j = 0; j < 25; ++j, r += 8) {
        float4 v = reinterpret_cast<const float4*>(X)[(size_t)r * 32 + c4];
        s.x += v.x; s.y += v.y; s.z += v.z; s.w += v.w;
        q.x += v.x * v.x; q.y += v.y * v.y; q.z += v.z * v.z; q.w += v.w * v.w;
    }
    __shared__ float sm[8][256];
    sm[rg][c4 * 4 + 0] = s.x; sm[rg][c4 * 4 + 1] = s.y;
    sm[rg][c4 * 4 + 2] = s.z; sm[rg][c4 * 4 + 3] = s.w;
    sm[rg][128 + c4 * 4 + 0] = q.x; sm[rg][128 + c4 * 4 + 1] = q.y;
    sm[rg][128 + c4 * 4 + 2] = q.z; sm[rg][128 + c4 * 4 + 3] = q.w;
    __syncthreads();
    float acc = 0.f;
#pragma unroll
    for (int g = 0; g < 8; ++g) acc += sm[g][t];
    atomicAdd(&stats[t], acc);
}

// ---------------- stats -> affine ----------------
__global__ void affine_k(const float* __restrict__ stats, const float* __restrict__ g,
                         const float* __restrict__ b, float* __restrict__ aff) {
    int t = threadIdx.x;
    const float invN = 1.0f / (float)N_NODES;
    float mean = stats[t] * invN;
    float var = stats[128 + t] * invN - mean * mean;
    float a = g[t] * rsqrtf(var + BN_EPS);
    aff[t] = a;
    aff[128 + t] = b[t] - mean * a;
}

// ---------------- pool raw input h into pooled[0] ----------------
__global__ void pool_in_k(const float* __restrict__ h, const int* __restrict__ gidx,
                          float* __restrict__ pooled) {
    int gid = blockIdx.x * 256 + threadIdx.x;
    int node = gid >> 5;
    int c = gid & 31;
    float4 v = reinterpret_cast<const float4*>(h)[(size_t)node * 32 + c];
    int gr = gidx[node];
    red_add_f32x4(pooled + (size_t)gr * DIM + c * 4, v);
}

// ---------------- H = relu(Z*a + c); pooled[layer] += H ----------------
__global__ void pool_act_k(const float* __restrict__ Z, const float* __restrict__ aff,
                           const int* __restrict__ gidx, float* __restrict__ H,
                           float* __restrict__ pooled) {
    int gid = blockIdx.x * 256 + threadIdx.x;
    int node = gid >> 5;
    int c = gid & 31;
    float4 v = reinterpret_cast<const float4*>(Z)[(size_t)node * 32 + c];
    float4 a4 = __ldg(reinterpret_cast<const float4*>(aff) + c);
    float4 c4 = __ldg(reinterpret_cast<const float4*>(aff + 128) + c);
    v.x = fmaxf(fmaf(v.x, a4.x, c4.x), 0.f);
    v.y = fmaxf(fmaf(v.y, a4.y, c4.y), 0.f);
    v.z = fmaxf(fmaf(v.z, a4.z, c4.z), 0.f);
    v.w = fmaxf(fmaf(v.w, a4.w, c4.w), 0.f);
    reinterpret_cast<float4*>(H)[(size_t)node * 32 + c] = v;
    int gr = gidx[node];
    red_add_f32x4(pooled + (size_t)gr * DIM + c * 4, v);
}

// ---------------- final score ----------------
__global__ void score_k(const float* __restrict__ pooled, const float* __restrict__ predW,
                        const float* __restrict__ predb, float* __restrict__ out) {
    int g = blockIdx.x;
    int o = threadIdx.x;
    __shared__ float sp[5 * DIM];
    for (int idx = o; idx < 5 * DIM; idx += 64)
        sp[idx] = pooled[(size_t)(idx / DIM) * (N_GRAPHS * DIM) + (size_t)g * DIM + (idx % DIM)];
    __syncthreads();
    float acc = 0.f;
#pragma unroll
    for (int i = 0; i < 5; ++i) acc += predb[i * OUTD + o];
    for (int i = 0; i < 5; ++i) {
#pragma unroll 4
        for (int k = 0; k < DIM; ++k)
            acc = fmaf(sp[i * DIM + k], predW[((size_t)i * DIM + k) * OUTD + o], acc);
    }
    out[(size_t)g * OUTD + o] = acc;
}

// ---------------- launch ----------------
extern "C" void kernel_launch(void* const* d_in, const int* in_sizes, int n_in,
                              void* d_out, int out_size) {
    const float* h     = (const float*)d_in[0];
    const int*   esrc  = (const int*)  d_in[1];
    const int*   edst  = (const int*)  d_in[2];
    const int*   gids  = (const int*)  d_in[3];
    const float* W1    = (const float*)d_in[4];
    const float* bn1_g = (const float*)d_in[5];
    const float* bn1_b = (const float*)d_in[6];
    const float* W2    = (const float*)d_in[7];
    const float* bn2_g = (const float*)d_in[8];
    const float* bn2_b = (const float*)d_in[9];
    const float* predW = (const float*)d_in[10];
    const float* predb = (const float*)d_in[11];
    float* out = (float*)d_out;

    float *pH, *pZ, *pZ1, *pPooled, *pStats, *pAff1, *pAff2;
    uint32_t* pWF;
    int *pDeg, *pRS, *pCur, *pCSR;
    cudaGetSymbolAddress((void**)&pH, g_H);
    cudaGetSymbolAddress((void**)&pZ, g_Z);
    cudaGetSymbolAddress((void**)&pZ1, g_Z1);
    cudaGetSymbolAddress((void**)&pPooled, g_pooled);
    cudaGetSymbolAddress((void**)&pStats, g_stats);
    cudaGetSymbolAddress((void**)&pAff1, g_aff1);
    cudaGetSymbolAddress((void**)&pAff2, g_aff2);
    cudaGetSymbolAddress((void**)&pWF, g_WF);
    cudaGetSymbolAddress((void**)&pDeg, g_deg);
    cudaGetSymbolAddress((void**)&pRS, g_rowstart);
    cudaGetSymbolAddress((void**)&pCur, g_cursor);
    cudaGetSymbolAddress((void**)&pCSR, g_csr);

    const int GEMM_SMEM = 2 * 16384 * (int)sizeof(__nv_bfloat16);   // 65536
    cudaFuncSetAttribute(gemm_mma_k<false>, cudaFuncAttributeMaxDynamicSharedMemorySize, GEMM_SMEM);
    cudaFuncSetAttribute(gemm_mma_k<true>,  cudaFuncAttributeMaxDynamicSharedMemorySize, GEMM_SMEM);

    const int NODE_BLOCKS = (N_NODES * 32) / 256;   // 6250
    const int EDGE_BLOCKS = N_EDGES / 256;          // 3125
    const int GEMM_BLOCKS = (N_NODES + 127) / 128;  // 391

    // one-time per launch: weight fragments + CSR
    conv_w_k<<<256, 256>>>(W1, W2, pWF);
    cudaMemsetAsync(pDeg, 0, N_NODES * sizeof(int), 0);
    deg_k<<<EDGE_BLOCKS, 256>>>(edst, pDeg);
    scan_k<<<1, 1024>>>(pDeg, pRS, pCur);
    fill_k<<<EDGE_BLOCKS, 256>>>(esrc, edst, pCur, pCSR);

    cudaMemsetAsync(pPooled, 0, 5 * N_GRAPHS * DIM * sizeof(float), 0);
    pool_in_k<<<NODE_BLOCKS, 256>>>(h, gids, pPooled);

    for (int i = 0; i < 4; ++i) {
        const float* Hsrc = (i == 0) ? h : pH;
        agg_k<<<NODE_BLOCKS, 256>>>(Hsrc, pRS, pCSR, pZ);

        gemm_mma_k<false><<<GEMM_BLOCKS, 256, GEMM_SMEM>>>(
            pZ, (const uint4*)(pWF + (size_t)i * 16384), pZ1, nullptr);
        cudaMemsetAsync(pStats, 0, 256 * sizeof(float), 0);
        stats_k<<<250, 256>>>(pZ1, pStats);
        affine_k<<<1, 128>>>(pStats, bn1_g + i * DIM, bn1_b + i * DIM, pAff1);

        gemm_mma_k<true><<<GEMM_BLOCKS, 256, GEMM_SMEM>>>(
            pZ1, (const uint4*)(pWF + (size_t)(4 + i) * 16384), pZ, pAff1);
        cudaMemsetAsync(pStats, 0, 256 * sizeof(float), 0);
        stats_k<<<250, 256>>>(pZ, pStats);
        affine_k<<<1, 128>>>(pStats, bn2_g + i * DIM, bn2_b + i * DIM, pAff2);

        pool_act_k<<<NODE_BLOCKS, 256>>>(pZ, pAff2, gids, pH,
                                         pPooled + (size_t)(i + 1) * N_GRAPHS * DIM);
    }

    score_k<<<N_GRAPHS, OUTD>>>(pPooled, predW, predb, out);
}